// round 1
// baseline (speedup 1.0000x reference)
#include <cuda_runtime.h>
#include <math.h>

#define B_  4
#define S_  2048
#define D_  1024
#define H_  16
#define HD_ 64
#define MS_ (B_*S_)   // 8192

// Scratch (static device globals — no allocation)
__device__ float g_Q[(size_t)MS_ * D_];
__device__ float g_K[(size_t)MS_ * D_];
__device__ float g_V[(size_t)MS_ * D_];
__device__ float g_C[(size_t)MS_ * D_];

// ---------------------------------------------------------------------------
// Generic fp32 GEMM + bias: C[M,N] = A[M,K] @ W[K,N] + bias[N]
// BM=BN=128, BK=8, 256 threads, 8x8 per thread.
// ---------------------------------------------------------------------------
__global__ __launch_bounds__(256) void sgemm_bias(
    const float* __restrict__ A, const float* __restrict__ W,
    const float* __restrict__ bias, float* __restrict__ C,
    int M, int N, int K)
{
    __shared__ float As[8][128];
    __shared__ float Bs[8][128];

    int tid = threadIdx.x;
    int tx = tid & 15, ty = tid >> 4;

    const float* Ab = A + (size_t)blockIdx.y * 128 * K;
    const float* Wb = W + blockIdx.x * 128;

    float acc[8][8];
#pragma unroll
    for (int i = 0; i < 8; i++)
#pragma unroll
        for (int j = 0; j < 8; j++) acc[i][j] = 0.f;

    int arow = tid >> 1;          // 0..127
    int acol = (tid & 1) * 4;     // 0 or 4
    int wrow = tid >> 5;          // 0..7
    int wcol = (tid & 31) * 4;    // 0..124

    for (int k0 = 0; k0 < K; k0 += 8) {
        float4 av = *(const float4*)(Ab + (size_t)arow * K + k0 + acol);
        As[acol + 0][arow] = av.x;
        As[acol + 1][arow] = av.y;
        As[acol + 2][arow] = av.z;
        As[acol + 3][arow] = av.w;
        *(float4*)(&Bs[wrow][wcol]) =
            *(const float4*)(Wb + (size_t)(k0 + wrow) * N + wcol);
        __syncthreads();
#pragma unroll
        for (int kk = 0; kk < 8; kk++) {
            float4 a0 = *(float4*)(&As[kk][ty * 8]);
            float4 a1 = *(float4*)(&As[kk][ty * 8 + 4]);
            float4 b0 = *(float4*)(&Bs[kk][tx * 8]);
            float4 b1 = *(float4*)(&Bs[kk][tx * 8 + 4]);
            float a[8] = {a0.x, a0.y, a0.z, a0.w, a1.x, a1.y, a1.z, a1.w};
            float b[8] = {b0.x, b0.y, b0.z, b0.w, b1.x, b1.y, b1.z, b1.w};
#pragma unroll
            for (int i = 0; i < 8; i++)
#pragma unroll
                for (int j = 0; j < 8; j++)
                    acc[i][j] = fmaf(a[i], b[j], acc[i][j]);
        }
        __syncthreads();
    }

    int row0 = blockIdx.y * 128 + ty * 8;
    int col0 = blockIdx.x * 128 + tx * 8;
    float4 bi0 = *(const float4*)(bias + col0);
    float4 bi1 = *(const float4*)(bias + col0 + 4);
#pragma unroll
    for (int i = 0; i < 8; i++) {
        float4 o0, o1;
        o0.x = acc[i][0] + bi0.x; o0.y = acc[i][1] + bi0.y;
        o0.z = acc[i][2] + bi0.z; o0.w = acc[i][3] + bi0.w;
        o1.x = acc[i][4] + bi1.x; o1.y = acc[i][5] + bi1.y;
        o1.z = acc[i][6] + bi1.z; o1.w = acc[i][7] + bi1.w;
        *(float4*)(C + (size_t)(row0 + i) * N + col0)     = o0;
        *(float4*)(C + (size_t)(row0 + i) * N + col0 + 4) = o1;
    }
}

// ---------------------------------------------------------------------------
// Scores: attn_raw[bh, q, k] = (Q[b,q,h,:] . K[b,k,h,:]) / 8
// 128x128 output tile per block, K-dim = 64 in 4 chunks of 16.
// grid (16, 16, 64), 256 threads.
// ---------------------------------------------------------------------------
__global__ __launch_bounds__(256) void scores_kernel(float* __restrict__ attn)
{
    __shared__ float Qs[16][128];
    __shared__ float Ks[16][128];

    int tid = threadIdx.x;
    int tx = tid & 15, ty = tid >> 4;
    int bh = blockIdx.z;
    int b = bh >> 4, h = bh & 15;

    const float* Qb = g_Q + (size_t)b * S_ * D_ + h * HD_;
    const float* Kb = g_K + (size_t)b * S_ * D_ + h * HD_;
    int q0 = blockIdx.y * 128;
    int k0 = blockIdx.x * 128;

    float acc[8][8];
#pragma unroll
    for (int i = 0; i < 8; i++)
#pragma unroll
        for (int j = 0; j < 8; j++) acc[i][j] = 0.f;

    for (int kt = 0; kt < HD_; kt += 16) {
#pragma unroll
        for (int l = 0; l < 2; l++) {
            int idx = tid * 2 + l;       // 0..511
            int row = idx >> 2;          // 0..127
            int c4  = (idx & 3) * 4;     // 0,4,8,12
            float4 v = *(const float4*)(Qb + (size_t)(q0 + row) * D_ + kt + c4);
            Qs[c4 + 0][row] = v.x; Qs[c4 + 1][row] = v.y;
            Qs[c4 + 2][row] = v.z; Qs[c4 + 3][row] = v.w;
            float4 w = *(const float4*)(Kb + (size_t)(k0 + row) * D_ + kt + c4);
            Ks[c4 + 0][row] = w.x; Ks[c4 + 1][row] = w.y;
            Ks[c4 + 2][row] = w.z; Ks[c4 + 3][row] = w.w;
        }
        __syncthreads();
#pragma unroll
        for (int kk = 0; kk < 16; kk++) {
            float4 a0 = *(float4*)(&Qs[kk][ty * 8]);
            float4 a1 = *(float4*)(&Qs[kk][ty * 8 + 4]);
            float4 b0 = *(float4*)(&Ks[kk][tx * 8]);
            float4 b1 = *(float4*)(&Ks[kk][tx * 8 + 4]);
            float a[8] = {a0.x, a0.y, a0.z, a0.w, a1.x, a1.y, a1.z, a1.w};
            float bb[8] = {b0.x, b0.y, b0.z, b0.w, b1.x, b1.y, b1.z, b1.w};
#pragma unroll
            for (int i = 0; i < 8; i++)
#pragma unroll
                for (int j = 0; j < 8; j++)
                    acc[i][j] = fmaf(a[i], bb[j], acc[i][j]);
        }
        __syncthreads();
    }

    const float scale = 0.125f;  // 1/sqrt(64)
    size_t base = (size_t)bh * S_ * S_;
#pragma unroll
    for (int i = 0; i < 8; i++) {
        size_t r = base + (size_t)(q0 + ty * 8 + i) * S_ + k0 + tx * 8;
        float4 o0, o1;
        o0.x = acc[i][0] * scale; o0.y = acc[i][1] * scale;
        o0.z = acc[i][2] * scale; o0.w = acc[i][3] * scale;
        o1.x = acc[i][4] * scale; o1.y = acc[i][5] * scale;
        o1.z = acc[i][6] * scale; o1.w = acc[i][7] * scale;
        *(float4*)(attn + r)     = o0;
        *(float4*)(attn + r + 4) = o1;
    }
}

// ---------------------------------------------------------------------------
// In-place row softmax over attn rows of length 2048. One block per row.
// ---------------------------------------------------------------------------
__global__ __launch_bounds__(256) void softmax_kernel(float* __restrict__ attn)
{
    size_t row = blockIdx.x;
    float* p = attn + row * (size_t)S_;
    int t = threadIdx.x;

    float v[8];
    float m = -3.4e38f;
#pragma unroll
    for (int i = 0; i < 8; i++) {
        v[i] = p[t + i * 256];
        m = fmaxf(m, v[i]);
    }
    __shared__ float redm[8];
    __shared__ float reds[8];
#pragma unroll
    for (int o = 16; o > 0; o >>= 1) m = fmaxf(m, __shfl_xor_sync(0xffffffffu, m, o));
    if ((t & 31) == 0) redm[t >> 5] = m;
    __syncthreads();
    float mm = redm[0];
#pragma unroll
    for (int i = 1; i < 8; i++) mm = fmaxf(mm, redm[i]);

    float s = 0.f;
#pragma unroll
    for (int i = 0; i < 8; i++) {
        v[i] = __expf(v[i] - mm);
        s += v[i];
    }
#pragma unroll
    for (int o = 16; o > 0; o >>= 1) s += __shfl_xor_sync(0xffffffffu, s, o);
    if ((t & 31) == 0) reds[t >> 5] = s;
    __syncthreads();
    float ss = reds[0];
#pragma unroll
    for (int i = 1; i < 8; i++) ss += reds[i];
    float rinv = 1.0f / ss;
#pragma unroll
    for (int i = 0; i < 8; i++) p[t + i * 256] = v[i] * rinv;
}

// ---------------------------------------------------------------------------
// Context: C[b,q,h,:] = sum_k attn[bh,q,k] * V[b,k,h,:]
// 128 q-rows x 64 d-cols per block, BK=16. grid (16, 64), 256 threads (8x4/thr).
// ---------------------------------------------------------------------------
__global__ __launch_bounds__(256) void context_kernel(const float* __restrict__ attn)
{
    __shared__ float As[16][128];
    __shared__ float Vs[16][64];

    int tid = threadIdx.x;
    int tx = tid & 15, ty = tid >> 4;
    int bh = blockIdx.y;
    int b = bh >> 4, h = bh & 15;

    const float* Ab = attn + (size_t)bh * S_ * S_ + (size_t)blockIdx.x * 128 * S_;
    const float* Vb = g_V + (size_t)b * S_ * D_ + h * HD_;
    float* Cb = g_C + ((size_t)b * S_ + blockIdx.x * 128) * D_ + h * HD_;

    float acc[8][4];
#pragma unroll
    for (int i = 0; i < 8; i++)
#pragma unroll
        for (int j = 0; j < 4; j++) acc[i][j] = 0.f;

    int vrow = tid >> 4;          // 0..15
    int vcol = (tid & 15) * 4;    // 0..60

    for (int k0 = 0; k0 < S_; k0 += 16) {
#pragma unroll
        for (int l = 0; l < 2; l++) {
            int idx = tid * 2 + l;
            int row = idx >> 2;
            int c4  = (idx & 3) * 4;
            float4 v = *(const float4*)(Ab + (size_t)row * S_ + k0 + c4);
            As[c4 + 0][row] = v.x; As[c4 + 1][row] = v.y;
            As[c4 + 2][row] = v.z; As[c4 + 3][row] = v.w;
        }
        *(float4*)(&Vs[vrow][vcol]) =
            *(const float4*)(Vb + (size_t)(k0 + vrow) * D_ + vcol);
        __syncthreads();
#pragma unroll
        for (int kk = 0; kk < 16; kk++) {
            float4 a0 = *(float4*)(&As[kk][ty * 8]);
            float4 a1 = *(float4*)(&As[kk][ty * 8 + 4]);
            float4 bv = *(float4*)(&Vs[kk][tx * 4]);
            float a[8] = {a0.x, a0.y, a0.z, a0.w, a1.x, a1.y, a1.z, a1.w};
            float bb[4] = {bv.x, bv.y, bv.z, bv.w};
#pragma unroll
            for (int i = 0; i < 8; i++)
#pragma unroll
                for (int j = 0; j < 4; j++)
                    acc[i][j] = fmaf(a[i], bb[j], acc[i][j]);
        }
        __syncthreads();
    }
#pragma unroll
    for (int i = 0; i < 8; i++) {
        float4 o;
        o.x = acc[i][0]; o.y = acc[i][1]; o.z = acc[i][2]; o.w = acc[i][3];
        *(float4*)(Cb + (size_t)(ty * 8 + i) * D_ + tx * 4) = o;
    }
}

// ---------------------------------------------------------------------------
extern "C" void kernel_launch(void* const* d_in, const int* in_sizes, int n_in,
                              void* d_out, int out_size)
{
    const float* q  = (const float*)d_in[0];
    const float* k  = (const float*)d_in[1];
    const float* v  = (const float*)d_in[2];
    const float* Wq = (const float*)d_in[3];
    const float* bq = (const float*)d_in[4];
    const float* Wk = (const float*)d_in[5];
    const float* bk = (const float*)d_in[6];
    const float* Wv = (const float*)d_in[7];
    const float* bv = (const float*)d_in[8];
    const float* Wo = (const float*)d_in[9];
    const float* bo = (const float*)d_in[10];

    float* out  = (float*)d_out;
    float* attn = out + (size_t)MS_ * D_;   // tuple order: (output, attention)

    float *pQ, *pK, *pV, *pC;
    cudaGetSymbolAddress((void**)&pQ, g_Q);
    cudaGetSymbolAddress((void**)&pK, g_K);
    cudaGetSymbolAddress((void**)&pV, g_V);
    cudaGetSymbolAddress((void**)&pC, g_C);

    dim3 gp(D_ / 128, MS_ / 128);  // (8, 64)
    sgemm_bias<<<gp, 256>>>(q, Wq, bq, pQ, MS_, D_, D_);
    sgemm_bias<<<gp, 256>>>(k, Wk, bk, pK, MS_, D_, D_);
    sgemm_bias<<<gp, 256>>>(v, Wv, bv, pV, MS_, D_, D_);

    scores_kernel<<<dim3(16, 16, 64), 256>>>(attn);
    softmax_kernel<<<B_ * H_ * S_, 256>>>(attn);
    context_kernel<<<dim3(16, 64), 256>>>(attn);

    sgemm_bias<<<gp, 256>>>(pC, Wo, bo, out, MS_, D_, D_);
}

// round 3
// speedup vs baseline: 2.0317x; 2.0317x over previous
#include <cuda_runtime.h>
#include <math.h>
#include <stdint.h>

#define B_  4
#define S_  2048
#define D_  1024
#define H_  16
#define HD_ 64
#define MS_ (B_*S_)   // 8192

// Scratch (static device globals — no allocation)
__device__ float g_Q[(size_t)MS_ * D_];
__device__ float g_K[(size_t)MS_ * D_];
__device__ float g_V[(size_t)MS_ * D_];
__device__ float g_C[(size_t)MS_ * D_];
__device__ float g_WT[4][(size_t)D_ * D_];   // transposed weights [n][k]

// ---------------------------------------------------------------------------
// tf32 helpers (sm_80+ ISA — compiles for plain sm_103 target)
// ---------------------------------------------------------------------------
__device__ __forceinline__ float f2tf(float f) {
    uint32_t u;
    asm("cvt.rna.tf32.f32 %0, %1;" : "=r"(u) : "f"(f));
    return __uint_as_float(u);
}

__device__ __forceinline__ void mma_tf32(float* d, const uint32_t* a, const uint32_t* b) {
    asm volatile(
        "mma.sync.aligned.m16n8k8.row.col.f32.tf32.tf32.f32 "
        "{%0,%1,%2,%3}, {%4,%5,%6,%7}, {%8,%9}, {%0,%1,%2,%3};"
        : "+f"(d[0]), "+f"(d[1]), "+f"(d[2]), "+f"(d[3])
        : "r"(a[0]), "r"(a[1]), "r"(a[2]), "r"(a[3]),
          "r"(b[0]), "r"(b[1]));
}

// ===========================================================================
// Weight transpose: out[n][k] = in[k][n], 1024x1024
// ===========================================================================
__global__ __launch_bounds__(256) void transpose1024(
    const float* __restrict__ in, float* __restrict__ out)
{
    __shared__ float t[32][33];
    int x = blockIdx.x * 32 + threadIdx.x;
    int y = blockIdx.y * 32 + threadIdx.y;
#pragma unroll
    for (int j = 0; j < 32; j += 8)
        t[threadIdx.y + j][threadIdx.x] = in[(size_t)(y + j) * D_ + x];
    __syncthreads();
    x = blockIdx.y * 32 + threadIdx.x;
    y = blockIdx.x * 32 + threadIdx.y;
#pragma unroll
    for (int j = 0; j < 32; j += 8)
        out[(size_t)(y + j) * D_ + x] = t[threadIdx.x][threadIdx.y + j];
}

// ===========================================================================
// tf32 MMA GEMM + bias: C[M,N] = A[M,K] @ BT[N,K]^T + bias[N]
// 128x128 tile, BK=32, 256 threads = 8 warps (2 x 4), warp tile 64x32.
// ===========================================================================
__global__ __launch_bounds__(256) void mma_gemm_bias(
    const float* __restrict__ A, const float* __restrict__ BT,
    const float* __restrict__ bias, float* __restrict__ C,
    int M, int N, int K)
{
    __shared__ float As[128][36];   // [m][k]
    __shared__ float Bs[128][36];   // [n][k]

    int tid  = threadIdx.x;
    int lane = tid & 31, warp = tid >> 5;
    int g = lane >> 2, t = lane & 3;
    int wm = warp >> 2, wn = warp & 3;

    int m0 = blockIdx.y * 128, n0 = blockIdx.x * 128;

    float acc[4][4][4];
#pragma unroll
    for (int i = 0; i < 4; i++)
#pragma unroll
        for (int j = 0; j < 4; j++)
#pragma unroll
            for (int r = 0; r < 4; r++) acc[i][j][r] = 0.f;

    for (int k0 = 0; k0 < K; k0 += 32) {
        __syncthreads();
#pragma unroll
        for (int p = 0; p < 4; p++) {
            int f4 = p * 256 + tid;
            int r = f4 >> 3, c4 = (f4 & 7) * 4;
            float4 va = *(const float4*)(A + (size_t)(m0 + r) * K + k0 + c4);
            As[r][c4 + 0] = f2tf(va.x); As[r][c4 + 1] = f2tf(va.y);
            As[r][c4 + 2] = f2tf(va.z); As[r][c4 + 3] = f2tf(va.w);
            float4 vb = *(const float4*)(BT + (size_t)(n0 + r) * K + k0 + c4);
            Bs[r][c4 + 0] = f2tf(vb.x); Bs[r][c4 + 1] = f2tf(vb.y);
            Bs[r][c4 + 2] = f2tf(vb.z); Bs[r][c4 + 3] = f2tf(vb.w);
        }
        __syncthreads();

#pragma unroll
        for (int kk = 0; kk < 32; kk += 8) {
            uint32_t af[4][4], bf[4][2];
#pragma unroll
            for (int mi = 0; mi < 4; mi++) {
                int mr = wm * 64 + mi * 16 + g;
                af[mi][0] = __float_as_uint(As[mr][kk + t]);
                af[mi][1] = __float_as_uint(As[mr + 8][kk + t]);
                af[mi][2] = __float_as_uint(As[mr][kk + t + 4]);
                af[mi][3] = __float_as_uint(As[mr + 8][kk + t + 4]);
            }
#pragma unroll
            for (int ni = 0; ni < 4; ni++) {
                int nr = wn * 32 + ni * 8 + g;
                bf[ni][0] = __float_as_uint(Bs[nr][kk + t]);
                bf[ni][1] = __float_as_uint(Bs[nr][kk + t + 4]);
            }
#pragma unroll
            for (int mi = 0; mi < 4; mi++)
#pragma unroll
                for (int ni = 0; ni < 4; ni++)
                    mma_tf32(acc[mi][ni], af[mi], bf[ni]);
        }
    }

#pragma unroll
    for (int mi = 0; mi < 4; mi++) {
        int row = m0 + wm * 64 + mi * 16 + g;
#pragma unroll
        for (int ni = 0; ni < 4; ni++) {
            int col = n0 + wn * 32 + ni * 8 + 2 * t;
            float2 b2 = *(const float2*)(bias + col);
            float2 o0, o1;
            o0.x = acc[mi][ni][0] + b2.x; o0.y = acc[mi][ni][1] + b2.y;
            o1.x = acc[mi][ni][2] + b2.x; o1.y = acc[mi][ni][3] + b2.y;
            *(float2*)(C + (size_t)row * N + col)       = o0;
            *(float2*)(C + (size_t)(row + 8) * N + col) = o1;
        }
    }
}

// ===========================================================================
// Scores via tf32 MMA: attn[bh,q,k] = (Q . K) / 8
// 128x128 tile per CTA, K-dim 64 in 2 chunks of 32. grid (16,16,64).
// ===========================================================================
__global__ __launch_bounds__(256) void scores_mma(float* __restrict__ attn)
{
    __shared__ float As[128][36];   // Q tile [q][hd]
    __shared__ float Bs[128][36];   // K tile [key][hd]

    int tid  = threadIdx.x;
    int lane = tid & 31, warp = tid >> 5;
    int g = lane >> 2, t = lane & 3;
    int wm = warp >> 2, wn = warp & 3;

    int bh = blockIdx.z;
    int b = bh >> 4, h = bh & 15;
    const float* Qb = g_Q + (size_t)b * S_ * D_ + h * HD_;
    const float* Kb = g_K + (size_t)b * S_ * D_ + h * HD_;
    int m0 = blockIdx.y * 128, n0 = blockIdx.x * 128;

    float acc[4][4][4];
#pragma unroll
    for (int i = 0; i < 4; i++)
#pragma unroll
        for (int j = 0; j < 4; j++)
#pragma unroll
            for (int r = 0; r < 4; r++) acc[i][j][r] = 0.f;

#pragma unroll
    for (int k0 = 0; k0 < HD_; k0 += 32) {
        __syncthreads();
#pragma unroll
        for (int p = 0; p < 4; p++) {
            int f4 = p * 256 + tid;
            int r = f4 >> 3, c4 = (f4 & 7) * 4;
            float4 va = *(const float4*)(Qb + (size_t)(m0 + r) * D_ + k0 + c4);
            As[r][c4 + 0] = f2tf(va.x); As[r][c4 + 1] = f2tf(va.y);
            As[r][c4 + 2] = f2tf(va.z); As[r][c4 + 3] = f2tf(va.w);
            float4 vb = *(const float4*)(Kb + (size_t)(n0 + r) * D_ + k0 + c4);
            Bs[r][c4 + 0] = f2tf(vb.x); Bs[r][c4 + 1] = f2tf(vb.y);
            Bs[r][c4 + 2] = f2tf(vb.z); Bs[r][c4 + 3] = f2tf(vb.w);
        }
        __syncthreads();

#pragma unroll
        for (int kk = 0; kk < 32; kk += 8) {
            uint32_t af[4][4], bf[4][2];
#pragma unroll
            for (int mi = 0; mi < 4; mi++) {
                int mr = wm * 64 + mi * 16 + g;
                af[mi][0] = __float_as_uint(As[mr][kk + t]);
                af[mi][1] = __float_as_uint(As[mr + 8][kk + t]);
                af[mi][2] = __float_as_uint(As[mr][kk + t + 4]);
                af[mi][3] = __float_as_uint(As[mr + 8][kk + t + 4]);
            }
#pragma unroll
            for (int ni = 0; ni < 4; ni++) {
                int nr = wn * 32 + ni * 8 + g;
                bf[ni][0] = __float_as_uint(Bs[nr][kk + t]);
                bf[ni][1] = __float_as_uint(Bs[nr][kk + t + 4]);
            }
#pragma unroll
            for (int mi = 0; mi < 4; mi++)
#pragma unroll
                for (int ni = 0; ni < 4; ni++)
                    mma_tf32(acc[mi][ni], af[mi], bf[ni]);
        }
    }

    const float scale = 0.125f;
    size_t base = (size_t)bh * S_ * S_;
#pragma unroll
    for (int mi = 0; mi < 4; mi++) {
        int row = m0 + wm * 64 + mi * 16 + g;
#pragma unroll
        for (int ni = 0; ni < 4; ni++) {
            int col = n0 + wn * 32 + ni * 8 + 2 * t;
            float2 o0, o1;
            o0.x = acc[mi][ni][0] * scale; o0.y = acc[mi][ni][1] * scale;
            o1.x = acc[mi][ni][2] * scale; o1.y = acc[mi][ni][3] * scale;
            *(float2*)(attn + base + (size_t)row * S_ + col)       = o0;
            *(float2*)(attn + base + (size_t)(row + 8) * S_ + col) = o1;
        }
    }
}

// ===========================================================================
// Context via tf32 MMA: C[b,q,h,:] = sum_k attn[bh,q,k] * V[b,k,h,:]
// 128(q) x 64(hd) tile, BK=32. 8 warps as 4x2, warp tile 32x32. grid (16,64).
// ===========================================================================
__global__ __launch_bounds__(256) void context_mma(const float* __restrict__ attn)
{
    __shared__ float As[128][36];   // attn tile [q][kpos]
    __shared__ float Vs[64][36];    // V^T tile  [hd][kpos]

    int tid  = threadIdx.x;
    int lane = tid & 31, warp = tid >> 5;
    int g = lane >> 2, t = lane & 3;
    int wm = warp >> 1, wn = warp & 1;   // 4 x 2

    int bh = blockIdx.y;
    int b = bh >> 4, h = bh & 15;
    const float* Ab = attn + (size_t)bh * S_ * S_;
    const float* Vb = g_V + (size_t)b * S_ * D_ + h * HD_;
    int m0 = blockIdx.x * 128;

    float acc[2][4][4];
#pragma unroll
    for (int i = 0; i < 2; i++)
#pragma unroll
        for (int j = 0; j < 4; j++)
#pragma unroll
            for (int r = 0; r < 4; r++) acc[i][j][r] = 0.f;

    for (int k0 = 0; k0 < S_; k0 += 32) {
        __syncthreads();
#pragma unroll
        for (int p = 0; p < 4; p++) {
            int f4 = p * 256 + tid;
            int r = f4 >> 3, c4 = (f4 & 7) * 4;
            float4 va = *(const float4*)(Ab + (size_t)(m0 + r) * S_ + k0 + c4);
            As[r][c4 + 0] = f2tf(va.x); As[r][c4 + 1] = f2tf(va.y);
            As[r][c4 + 2] = f2tf(va.z); As[r][c4 + 3] = f2tf(va.w);
        }
#pragma unroll
        for (int p = 0; p < 2; p++) {
            int f4 = p * 256 + tid;
            int kr = f4 >> 4, c4 = (f4 & 15) * 4;
            float4 vv = *(const float4*)(Vb + (size_t)(k0 + kr) * D_ + c4);
            Vs[c4 + 0][kr] = f2tf(vv.x); Vs[c4 + 1][kr] = f2tf(vv.y);
            Vs[c4 + 2][kr] = f2tf(vv.z); Vs[c4 + 3][kr] = f2tf(vv.w);
        }
        __syncthreads();

#pragma unroll
        for (int kk = 0; kk < 32; kk += 8) {
            uint32_t af[2][4], bf[4][2];
#pragma unroll
            for (int mi = 0; mi < 2; mi++) {
                int mr = wm * 32 + mi * 16 + g;
                af[mi][0] = __float_as_uint(As[mr][kk + t]);
                af[mi][1] = __float_as_uint(As[mr + 8][kk + t]);
                af[mi][2] = __float_as_uint(As[mr][kk + t + 4]);
                af[mi][3] = __float_as_uint(As[mr + 8][kk + t + 4]);
            }
#pragma unroll
            for (int ni = 0; ni < 4; ni++) {
                int nr = wn * 32 + ni * 8 + g;
                bf[ni][0] = __float_as_uint(Vs[nr][kk + t]);
                bf[ni][1] = __float_as_uint(Vs[nr][kk + t + 4]);
            }
#pragma unroll
            for (int mi = 0; mi < 2; mi++)
#pragma unroll
                for (int ni = 0; ni < 4; ni++)
                    mma_tf32(acc[mi][ni], af[mi], bf[ni]);
        }
    }

    float* Cb = g_C + (size_t)b * S_ * D_ + h * HD_;
#pragma unroll
    for (int mi = 0; mi < 2; mi++) {
        int row = m0 + wm * 32 + mi * 16 + g;
#pragma unroll
        for (int ni = 0; ni < 4; ni++) {
            int col = wn * 32 + ni * 8 + 2 * t;
            float2 o0, o1;
            o0.x = acc[mi][ni][0]; o0.y = acc[mi][ni][1];
            o1.x = acc[mi][ni][2]; o1.y = acc[mi][ni][3];
            *(float2*)(Cb + (size_t)row * D_ + col)       = o0;
            *(float2*)(Cb + (size_t)(row + 8) * D_ + col) = o1;
        }
    }
}

// ---------------------------------------------------------------------------
// In-place row softmax over attn rows of length 2048.
// ---------------------------------------------------------------------------
__global__ __launch_bounds__(256) void softmax_kernel(float* __restrict__ attn)
{
    size_t row = blockIdx.x;
    float* p = attn + row * (size_t)S_;
    int t = threadIdx.x;

    float v[8];
    float m = -3.4e38f;
#pragma unroll
    for (int i = 0; i < 8; i++) {
        v[i] = p[t + i * 256];
        m = fmaxf(m, v[i]);
    }
    __shared__ float redm[8];
    __shared__ float reds[8];
#pragma unroll
    for (int o = 16; o > 0; o >>= 1) m = fmaxf(m, __shfl_xor_sync(0xffffffffu, m, o));
    if ((t & 31) == 0) redm[t >> 5] = m;
    __syncthreads();
    float mm = redm[0];
#pragma unroll
    for (int i = 1; i < 8; i++) mm = fmaxf(mm, redm[i]);

    float s = 0.f;
#pragma unroll
    for (int i = 0; i < 8; i++) {
        v[i] = __expf(v[i] - mm);
        s += v[i];
    }
#pragma unroll
    for (int o = 16; o > 0; o >>= 1) s += __shfl_xor_sync(0xffffffffu, s, o);
    if ((t & 31) == 0) reds[t >> 5] = s;
    __syncthreads();
    float ss = reds[0];
#pragma unroll
    for (int i = 1; i < 8; i++) ss += reds[i];
    float rinv = 1.0f / ss;
#pragma unroll
    for (int i = 0; i < 8; i++) p[t + i * 256] = v[i] * rinv;
}

// ---------------------------------------------------------------------------
extern "C" void kernel_launch(void* const* d_in, const int* in_sizes, int n_in,
                              void* d_out, int out_size)
{
    const float* q  = (const float*)d_in[0];
    const float* k  = (const float*)d_in[1];
    const float* v  = (const float*)d_in[2];
    const float* Wq = (const float*)d_in[3];
    const float* bq = (const float*)d_in[4];
    const float* Wk = (const float*)d_in[5];
    const float* bk = (const float*)d_in[6];
    const float* Wv = (const float*)d_in[7];
    const float* bv = (const float*)d_in[8];
    const float* Wo = (const float*)d_in[9];
    const float* bo = (const float*)d_in[10];

    float* out  = (float*)d_out;
    float* attn = out + (size_t)MS_ * D_;   // tuple order: (output, attention)

    float *pQ, *pK, *pV, *pC, *pWT;
    cudaGetSymbolAddress((void**)&pQ, g_Q);
    cudaGetSymbolAddress((void**)&pK, g_K);
    cudaGetSymbolAddress((void**)&pV, g_V);
    cudaGetSymbolAddress((void**)&pC, g_C);
    cudaGetSymbolAddress((void**)&pWT, g_WT);

    float* WTq = pWT + 0 * (size_t)D_ * D_;
    float* WTk = pWT + 1 * (size_t)D_ * D_;
    float* WTv = pWT + 2 * (size_t)D_ * D_;
    float* WTo = pWT + 3 * (size_t)D_ * D_;

    dim3 tb(32, 8), tg(32, 32);
    transpose1024<<<tg, tb>>>(Wq, WTq);
    transpose1024<<<tg, tb>>>(Wk, WTk);
    transpose1024<<<tg, tb>>>(Wv, WTv);
    transpose1024<<<tg, tb>>>(Wo, WTo);

    dim3 gp(D_ / 128, MS_ / 128);  // (8, 64)
    mma_gemm_bias<<<gp, 256>>>(q, WTq, bq, pQ, MS_, D_, D_);
    mma_gemm_bias<<<gp, 256>>>(k, WTk, bk, pK, MS_, D_, D_);
    mma_gemm_bias<<<gp, 256>>>(v, WTv, bv, pV, MS_, D_, D_);

    scores_mma<<<dim3(16, 16, 64), 256>>>(attn);
    softmax_kernel<<<B_ * H_ * S_, 256>>>(attn);
    context_mma<<<dim3(16, 64), 256>>>(attn);

    mma_gemm_bias<<<gp, 256>>>(pC, WTo, bo, out, MS_, D_, D_);
}